// round 12
// baseline (speedup 1.0000x reference)
#include <cuda_runtime.h>
#include <cuda_fp16.h>
#include <cstdint>

// ===========================================================================
// mie_51281909514553 — 3-layer expert-merged MLP, pure fp16 HMMA
// R12: ONE persistent kernel, dynamic tile queue, cross-layer rowblock
//      dataflow (removes wave-quantization tails + launch gaps).
// Queue: [cast(128), merge0(512), L0(512), merge1(1024), L1(512),
//         merge2(512), L2(256)]  = 3456 tiles.
// ===========================================================================

#define E_EXPERTS 8

// ------------------------------ scratch (no allocs allowed) ----------------
__device__ __half g_xh[8192 * 1024];
__device__ __half g_act0[8192 * 1024];
__device__ __half g_wt0[1024 * 512];       // merged W^T: [N][K] fp16
__device__ __half g_wt1[1024 * 1024];
__device__ __half g_wt2[512 * 1024];
__device__ float g_bm0[1024];
__device__ float g_bm1[1024];
__device__ float g_bm2[512];

// ------------------------------ scheduler state ----------------------------
__device__ int g_next;
__device__ int g_cast_done;                // -> 128
__device__ int g_md0, g_md1, g_md2;        // -> 512 / 1024 / 512
__device__ int g_rb0[64], g_rb1[64];       // rowblock done counts (-> 8)

__global__ void init_state() {
    if (threadIdx.x == 0) { g_next = 0; g_cast_done = 0; g_md0 = 0; g_md1 = 0; g_md2 = 0; }
    if (threadIdx.x < 64) { g_rb0[threadIdx.x] = 0; g_rb1[threadIdx.x] = 0; }
}

// queue layout
#define Q_CAST   0
#define Q_M0     128
#define Q_L0     640
#define Q_M1     1152
#define Q_L1     2176
#define Q_M2     2688
#define Q_L2     3200
#define Q_TOTAL  3456

// ------------------------------ helpers ------------------------------------
__device__ __forceinline__ uint32_t smem_u32(const void* p) {
    uint32_t a;
    asm("{ .reg .u64 t; cvta.to.shared.u64 t, %1; cvt.u32.u64 %0, t; }"
        : "=r"(a) : "l"(p));
    return a;
}
__device__ __forceinline__ void cp16(uint32_t s, const void* g) {
    asm volatile("cp.async.cg.shared.global [%0], [%1], 16;" :: "r"(s), "l"(g) : "memory");
}
#define CP_COMMIT() asm volatile("cp.async.commit_group;" ::: "memory")
#define CP_WAIT(n)  asm volatile("cp.async.wait_group %0;" :: "n"(n) : "memory")

__device__ __forceinline__ void ldsm4(uint32_t& r0, uint32_t& r1,
                                      uint32_t& r2, uint32_t& r3, uint32_t a) {
    asm volatile("ldmatrix.sync.aligned.m8n8.x4.shared.b16 {%0,%1,%2,%3}, [%4];"
                 : "=r"(r0), "=r"(r1), "=r"(r2), "=r"(r3) : "r"(a));
}
__device__ __forceinline__ void mma_f16(float* c, const uint32_t* a, const uint32_t* b) {
    asm volatile(
        "mma.sync.aligned.m16n8k16.row.col.f32.f16.f16.f32 "
        "{%0,%1,%2,%3}, {%4,%5,%6,%7}, {%8,%9}, {%0,%1,%2,%3};"
        : "+f"(c[0]), "+f"(c[1]), "+f"(c[2]), "+f"(c[3])
        : "r"(a[0]), "r"(a[1]), "r"(a[2]), "r"(a[3]), "r"(b[0]), "r"(b[1]));
}

__device__ __forceinline__ void cta_wait(int* p, int tgt) {
    if (threadIdx.x == 0) { while (atomicAdd(p, 0) < tgt) { } }
    __syncthreads();
}
__device__ __forceinline__ void cta_signal(int* p) {
    __threadfence();
    __syncthreads();
    if (threadIdx.x == 0) atomicAdd(p, 1);
}

// ------------------------------ tile bodies --------------------------------
// cast tile: 64 rows x 512 cols fp32 -> fp16
__device__ void cast_tile(const float* x, __half* xh, int ct) {
    const float4* x4 = reinterpret_cast<const float4*>(x) + (size_t)ct * 8192;
    __half2* o = reinterpret_cast<__half2*>(xh) + (size_t)ct * 16384;
    for (int j = threadIdx.x; j < 8192; j += 256) {
        float4 v = x4[j];
        __half2 a, b;
        a.x = __float2half_rn(v.x); a.y = __float2half_rn(v.y);
        b.x = __float2half_rn(v.z); b.y = __float2half_rn(v.w);
        o[2 * j] = a;
        o[2 * j + 1] = b;
    }
}

// merge tile: 32k x 32n of Wm^T (+ bias when kb==0)
__device__ void merge_tile(char* smem, const float* weights,
                           const float* W, const float* b,
                           __half* T, float* bm, int K, int N, int kb, int nb) {
    float* tile = reinterpret_cast<float*>(smem);   // [32][33]
    const int tx = threadIdx.x & 31, ty8 = threadIdx.x >> 5;

    float s = 0.f;
#pragma unroll
    for (int e = 0; e < E_EXPERTS; e++) s += weights[e];
    const float inv = 1.f / s;
    float wn[E_EXPERTS];
#pragma unroll
    for (int e = 0; e < E_EXPERTS; e++) wn[e] = weights[e] * inv;

    const int k0 = kb * 32, n0 = nb * 32;
    const size_t KN = (size_t)K * N;
    for (int ty = ty8; ty < 32; ty += 8) {
        float acc = 0.f;
        const float* src = W + (size_t)(k0 + ty) * N + n0 + tx;
#pragma unroll
        for (int e = 0; e < E_EXPERTS; e++) acc += wn[e] * src[e * KN];
        tile[ty * 33 + tx] = acc;
    }
    if (kb == 0 && threadIdx.x < 32) {
        float acc = 0.f;
#pragma unroll
        for (int e = 0; e < E_EXPERTS; e++) acc += wn[e] * b[e * N + n0 + threadIdx.x];
        bm[n0 + threadIdx.x] = acc;
    }
    __syncthreads();
    for (int ty = ty8; ty < 32; ty += 8)
        T[(size_t)(n0 + ty) * K + k0 + tx] = __float2half_rn(tile[tx * 33 + ty]);
}

// ------------------------------ GEMM tile ----------------------------------
#define BK 32
#define TSTRIDE 40
#define ROWB (TSTRIDE * 2)                  // 80 bytes
#define TILE_B (128 * ROWB)                 // 10240 bytes
#define STAGE_B (2 * TILE_B)
#define SMEM_DYN (2 * STAGE_B)              // 40960 -> 2 CTAs/SM

__device__ void gemm_tile(char* smem,
                          const __half* A, const __half* B,
                          const float* bias, const float* alpha,
                          float* outF, __half* outH,
                          int N, int K, int bm_idx, int bn_idx, bool out_half) {
    const uint32_t sbase = smem_u32(smem);
    const int tid = threadIdx.x;
    const int wid = tid >> 5, lane = tid & 31;
    const int gid = lane >> 2, tg = lane & 3;
    const int warp_m = (wid & 3) * 32;
    const int warp_n = (wid >> 2) * 64;
    const int block_m = bm_idx * 128;
    const int block_n = bn_idx * 128;

    uint32_t a_off[2];
#pragma unroll
    for (int mt = 0; mt < 2; mt++)
        a_off[mt] = ((warp_m + mt * 16 + (lane & 15)) * TSTRIDE + (lane >> 4) * 8) * 2;
    uint32_t b_off[4];
#pragma unroll
    for (int nt2 = 0; nt2 < 4; nt2++)
        b_off[nt2] = ((warp_n + nt2 * 16 + (lane >> 4) * 8 + (lane & 7)) * TSTRIDE +
                      ((lane >> 3) & 1) * 8) * 2;

    float acc[2][8][4];
#pragma unroll
    for (int mt = 0; mt < 2; mt++)
#pragma unroll
        for (int nt = 0; nt < 8; nt++)
#pragma unroll
            for (int j = 0; j < 4; j++) acc[mt][nt][j] = 0.f;

    const int nK = K / BK;

    auto load_stage = [&](int ki, int s) {
        const int k0 = ki * BK;
        const uint32_t base = sbase + (uint32_t)s * STAGE_B;
#pragma unroll
        for (int j = 0; j < 2; j++) {
            int chunk = j * 256 + tid;
            int r = chunk >> 2, c = chunk & 3;
            uint32_t so = (uint32_t)(r * ROWB + c * 16);
            cp16(base + so, A + (size_t)(block_m + r) * K + k0 + c * 8);
            cp16(base + TILE_B + so, B + (size_t)(block_n + r) * K + k0 + c * 8);
        }
    };

    load_stage(0, 0);
    CP_COMMIT();

    for (int i = 0; i < nK; i++) {
        CP_WAIT(0);
        __syncthreads();

        if (i + 1 < nK) load_stage(i + 1, (i + 1) & 1);
        CP_COMMIT();

        const uint32_t tA = sbase + (uint32_t)(i & 1) * STAGE_B;
        const uint32_t tB = tA + TILE_B;

#pragma unroll
        for (int ks = 0; ks < 2; ks++) {
            const uint32_t kb = ks * 32;
            uint32_t af[2][4];
#pragma unroll
            for (int mt = 0; mt < 2; mt++)
                ldsm4(af[mt][0], af[mt][1], af[mt][2], af[mt][3], tA + a_off[mt] + kb);
#pragma unroll
            for (int nt2 = 0; nt2 < 4; nt2++) {
                uint32_t bf[2][2];
                ldsm4(bf[0][0], bf[0][1], bf[1][0], bf[1][1], tB + b_off[nt2] + kb);
#pragma unroll
                for (int h = 0; h < 2; h++) {
                    const int nt = 2 * nt2 + h;
#pragma unroll
                    for (int mt = 0; mt < 2; mt++)
                        mma_f16(acc[mt][nt], af[mt], bf[h]);
                }
            }
        }
    }

    // epilogue: bias + PReLU
#pragma unroll
    for (int mt = 0; mt < 2; mt++) {
        const int r0 = block_m + warp_m + mt * 16 + gid;
#pragma unroll
        for (int nt = 0; nt < 8; nt++) {
            const int n = block_n + warp_n + nt * 8 + tg * 2;
            const float b0 = bias[n],  b1 = bias[n + 1];
            const float p0 = alpha[n], p1 = alpha[n + 1];
#pragma unroll
            for (int half = 0; half < 2; half++) {
                const int r = r0 + half * 8;
                float v0 = acc[mt][nt][half * 2 + 0] + b0;
                float v1 = acc[mt][nt][half * 2 + 1] + b1;
                v0 = v0 >= 0.f ? v0 : p0 * v0;
                v1 = v1 >= 0.f ? v1 : p1 * v1;
                if (out_half) {
                    __half2 hh;
                    hh.x = __float2half_rn(v0);
                    hh.y = __float2half_rn(v1);
                    *reinterpret_cast<__half2*>(&outH[(size_t)r * N + n]) = hh;
                } else {
                    float2 o; o.x = v0; o.y = v1;
                    *reinterpret_cast<float2*>(&outF[(size_t)r * N + n]) = o;
                }
            }
        }
    }
}

// ------------------------------ persistent scheduler -----------------------
__global__ __launch_bounds__(256, 2)
void mega(const float* __restrict__ x, const float* __restrict__ weights,
          const float* __restrict__ W0, const float* __restrict__ b0, const float* __restrict__ a0,
          const float* __restrict__ W1, const float* __restrict__ b1, const float* __restrict__ a1,
          const float* __restrict__ W2, const float* __restrict__ b2, const float* __restrict__ a2,
          float* __restrict__ out) {
    extern __shared__ char smem[];
    __shared__ int s_tile;

    for (;;) {
        __syncthreads();                       // protect smem + s_tile reuse
        if (threadIdx.x == 0) s_tile = atomicAdd(&g_next, 1);
        __syncthreads();
        const int t = s_tile;
        if (t >= Q_TOTAL) return;

        if (t < Q_M0) {                        // cast
            cast_tile(x, g_xh, t);
            cta_signal(&g_cast_done);
        } else if (t < Q_L0) {                 // merge layer-0 weights (16kb x 32nb)
            int u = t - Q_M0;
            merge_tile(smem, weights, W0, b0, g_wt0, g_bm0, 512, 1024, u >> 5, u & 31);
            cta_signal(&g_md0);
        } else if (t < Q_M1) {                 // GEMM layer 0
            int u = t - Q_L0;
            int m = u >> 3, n = u & 7;
            cta_wait(&g_cast_done, 128);
            cta_wait(&g_md0, 512);
            gemm_tile(smem, g_xh, g_wt0, g_bm0, a0, nullptr, g_act0,
                      1024, 512, m, n, true);
            cta_signal(&g_rb0[m]);
        } else if (t < Q_L1) {                 // merge layer-1 weights (32 x 32)
            int u = t - Q_M1;
            merge_tile(smem, weights, W1, b1, g_wt1, g_bm1, 1024, 1024, u >> 5, u & 31);
            cta_signal(&g_md1);
        } else if (t < Q_M2) {                 // GEMM layer 1
            int u = t - Q_L1;
            int m = u >> 3, n = u & 7;
            cta_wait(&g_md1, 1024);
            cta_wait(&g_rb0[m], 8);
            gemm_tile(smem, g_act0, g_wt1, g_bm1, a1, nullptr, g_xh,
                      1024, 1024, m, n, true);
            cta_signal(&g_rb1[m]);
        } else if (t < Q_L2) {                 // merge layer-2 weights (32kb x 16nb)
            int u = t - Q_M2;
            merge_tile(smem, weights, W2, b2, g_wt2, g_bm2, 1024, 512, u >> 4, u & 15);
            cta_signal(&g_md2);
        } else {                               // GEMM layer 2 -> fp32 out
            int u = t - Q_L2;
            int m = u >> 2, n = u & 3;
            cta_wait(&g_md2, 512);
            cta_wait(&g_rb1[m], 8);
            gemm_tile(smem, g_xh, g_wt2, g_bm2, a2, out, nullptr,
                      512, 1024, m, n, false);
        }
    }
}

// ------------------------------ launch -------------------------------------
extern "C" void kernel_launch(void* const* d_in, const int* in_sizes, int n_in,
                              void* d_out, int out_size) {
    const float* x       = (const float*)d_in[0];
    const float* weights = (const float*)d_in[1];
    const float* W0 = (const float*)d_in[2];
    const float* b0 = (const float*)d_in[3];
    const float* a0 = (const float*)d_in[4];
    const float* W1 = (const float*)d_in[5];
    const float* b1 = (const float*)d_in[6];
    const float* a1 = (const float*)d_in[7];
    const float* W2 = (const float*)d_in[8];
    const float* b2 = (const float*)d_in[9];
    const float* a2 = (const float*)d_in[10];
    float* out = (float*)d_out;

    static int grid = 0;
    if (grid == 0) {
        int sms = 0, dev = 0;
        cudaGetDevice(&dev);
        cudaDeviceGetAttribute(&sms, cudaDevAttrMultiProcessorCount, dev);
        if (sms <= 0) sms = 148;
        grid = 2 * sms;
        cudaFuncSetAttribute(mega, cudaFuncAttributeMaxDynamicSharedMemorySize, SMEM_DYN);
    }

    init_state<<<1, 128>>>();
    mega<<<grid, 256, SMEM_DYN>>>(x, weights, W0, b0, a0, W1, b1, a1,
                                  W2, b2, a2, out);
}

// round 13
// speedup vs baseline: 1.5915x; 1.5915x over previous
#include <cuda_runtime.h>
#include <cuda_fp16.h>
#include <cstdint>

// ===========================================================================
// mie_51281909514553 — 3-layer expert-merged MLP, pure fp16 HMMA
//   wn = weights/sum(weights); per layer: x = PReLU(x @ Wm + bm, a)
//   Weights + activations fp16 (RN), fp32 accumulate (HMMA ceiling:
//   512 MAC/cyc/SM measured). R13: R11 structure (best known, 157.6us)
//   + merge_w expert-gather via float4 loads (same 512-block geometry).
// ===========================================================================

#define M_ROWS 8192
#define E_EXPERTS 8

// ------------------------------ scratch (no allocs allowed) ----------------
__device__ __half g_xh[8192 * 1024];       // layer input activations (fp16)
__device__ __half g_a0[8192 * 1024];
__device__ __half g_wt0[1024 * 512];       // merged W^T: [N][K] fp16
__device__ __half g_wt1[1024 * 1024];
__device__ __half g_wt2[512 * 1024];
__device__ float g_bm0[1024];
__device__ float g_bm1[1024];
__device__ float g_bm2[512];

// ------------------------------ helpers ------------------------------------
__device__ __forceinline__ uint32_t smem_u32(const void* p) {
    uint32_t a;
    asm("{ .reg .u64 t; cvta.to.shared.u64 t, %1; cvt.u32.u64 %0, t; }"
        : "=r"(a) : "l"(p));
    return a;
}

__device__ __forceinline__ void cp16(uint32_t s, const void* g) {
    asm volatile("cp.async.cg.shared.global [%0], [%1], 16;" :: "r"(s), "l"(g) : "memory");
}
#define CP_COMMIT() asm volatile("cp.async.commit_group;" ::: "memory")
#define CP_WAIT(n)  asm volatile("cp.async.wait_group %0;" :: "n"(n) : "memory")

__device__ __forceinline__ void ldsm4(uint32_t& r0, uint32_t& r1,
                                      uint32_t& r2, uint32_t& r3, uint32_t a) {
    asm volatile("ldmatrix.sync.aligned.m8n8.x4.shared.b16 {%0,%1,%2,%3}, [%4];"
                 : "=r"(r0), "=r"(r1), "=r"(r2), "=r"(r3) : "r"(a));
}

__device__ __forceinline__ void mma_f16(float* c, const uint32_t* a, const uint32_t* b) {
    asm volatile(
        "mma.sync.aligned.m16n8k16.row.col.f32.f16.f16.f32 "
        "{%0,%1,%2,%3}, {%4,%5,%6,%7}, {%8,%9}, {%0,%1,%2,%3};"
        : "+f"(c[0]), "+f"(c[1]), "+f"(c[2]), "+f"(c[3])
        : "r"(a[0]), "r"(a[1]), "r"(a[2]), "r"(a[3]), "r"(b[0]), "r"(b[1]));
}

// ------------------------------ merge+transpose ----------------------------
// Wm^T[n][k] = sum_e wn_e W[e][k][n] -> fp16; bm[n] merged bias (fp32).
// 32x32 tiles (512/1024-block grids, proven high occupancy); float4 expert
// gather: thread -> (row kk = tid>>3, quad v = tid&7), 8 independent 16B
// loads. Scalar smem stores into pad-33 tile (16B-alignment-safe);
// transpose read tile[tx*33+ty] is conflict-free.
__global__ void merge_w(const float* __restrict__ weights,
                        const float* __restrict__ W,
                        const float* __restrict__ b,
                        __half* __restrict__ T,
                        float* __restrict__ bm,
                        int K, int N) {
    __shared__ float tile[32][33];
    const int tid = threadIdx.x;

    float s = 0.f;
#pragma unroll
    for (int e = 0; e < E_EXPERTS; e++) s += weights[e];
    const float inv = 1.f / s;
    float wn[E_EXPERTS];
#pragma unroll
    for (int e = 0; e < E_EXPERTS; e++) wn[e] = weights[e] * inv;

    const int k0 = blockIdx.x * 32, n0 = blockIdx.y * 32;
    const size_t KN = (size_t)K * N;

    {
        const int kk = tid >> 3;           // 0..31 row within tile
        const int v = tid & 7;             // 0..7 float4 within row
        const float* src = W + (size_t)(k0 + kk) * N + n0 + v * 4;
        float4 acc = make_float4(0.f, 0.f, 0.f, 0.f);
#pragma unroll
        for (int e = 0; e < E_EXPERTS; e++) {
            float4 w4 = *reinterpret_cast<const float4*>(src + (size_t)e * KN);
            acc.x = fmaf(wn[e], w4.x, acc.x);
            acc.y = fmaf(wn[e], w4.y, acc.y);
            acc.z = fmaf(wn[e], w4.z, acc.z);
            acc.w = fmaf(wn[e], w4.w, acc.w);
        }
        tile[kk][v * 4 + 0] = acc.x;
        tile[kk][v * 4 + 1] = acc.y;
        tile[kk][v * 4 + 2] = acc.z;
        tile[kk][v * 4 + 3] = acc.w;
    }

    if (blockIdx.x == 0 && tid < 32) {
        const int n = n0 + tid;
        float acc = 0.f;
#pragma unroll
        for (int e = 0; e < E_EXPERTS; e++) acc += wn[e] * b[e * N + n];
        bm[n] = acc;
    }
    __syncthreads();

    {
        const int tx = tid & 31;           // k within tile (coalesced out)
        for (int ty = tid >> 5; ty < 32; ty += 8)   // n within tile
            T[(size_t)(n0 + ty) * K + k0 + tx] = __float2half_rn(tile[tx][ty]);
    }
}

// fp32 -> fp16, vectorized (float4 in, half2x2 out)
__global__ void cast_x(const float4* __restrict__ x, __half2* __restrict__ xh, int n4) {
    int i = blockIdx.x * blockDim.x + threadIdx.x;
    if (i < n4) {
        float4 v = x[i];
        __half2 a, b;
        a.x = __float2half_rn(v.x); a.y = __float2half_rn(v.y);
        b.x = __float2half_rn(v.z); b.y = __float2half_rn(v.w);
        xh[2 * i] = a;
        xh[2 * i + 1] = b;
    }
}

// ------------------------------ HMMA GEMM ----------------------------------
// BM=128, BN=128, BK=32, 256 threads (8 warps: 4 M x 2 N), warp tile 32x64.
// 2-stage cp.async pipeline, one sync per chunk, 2 CTAs per SM.
#define BK 32
#define TSTRIDE 40
#define ROWB (TSTRIDE * 2)                  // 80 bytes
#define TILE_B (128 * ROWB)                 // 10240 bytes per tile
#define STAGE_B (2 * TILE_B)                // A, B = 20480 bytes
#define SMEM_DYN (2 * STAGE_B)              // 40960 bytes -> 2 CTAs/SM

template <int OUT_HALF>
__global__ __launch_bounds__(256, 2)
void gemm_hmma(const __half* __restrict__ A, const __half* __restrict__ B,
               const float* __restrict__ bias, const float* __restrict__ alpha,
               float* __restrict__ outF, __half* __restrict__ outH,
               int M, int N, int K) {
    extern __shared__ char smem[];
    const uint32_t sbase = smem_u32(smem);

    const int tid = threadIdx.x;
    const int wid = tid >> 5, lane = tid & 31;
    const int gid = lane >> 2, tg = lane & 3;
    const int warp_m = (wid & 3) * 32;
    const int warp_n = (wid >> 2) * 64;
    const int block_m = blockIdx.y * 128;
    const int block_n = blockIdx.x * 128;

    uint32_t a_off[2];
#pragma unroll
    for (int mt = 0; mt < 2; mt++)
        a_off[mt] = ((warp_m + mt * 16 + (lane & 15)) * TSTRIDE + (lane >> 4) * 8) * 2;
    uint32_t b_off[4];
#pragma unroll
    for (int nt2 = 0; nt2 < 4; nt2++)
        b_off[nt2] = ((warp_n + nt2 * 16 + (lane >> 4) * 8 + (lane & 7)) * TSTRIDE +
                      ((lane >> 3) & 1) * 8) * 2;

    float acc[2][8][4];
#pragma unroll
    for (int mt = 0; mt < 2; mt++)
#pragma unroll
        for (int nt = 0; nt < 8; nt++)
#pragma unroll
            for (int j = 0; j < 4; j++) acc[mt][nt][j] = 0.f;

    const int nK = K / BK;
    auto stg = [&](int s) { return sbase + (uint32_t)s * STAGE_B; };

    auto load_stage = [&](int ki, int s) {
        const int k0 = ki * BK;
        const uint32_t base = stg(s);
#pragma unroll
        for (int j = 0; j < 2; j++) {
            int chunk = j * 256 + tid;
            int r = chunk >> 2, c = chunk & 3;
            uint32_t so = (uint32_t)(r * ROWB + c * 16);
            cp16(base + so, A + (size_t)(block_m + r) * K + k0 + c * 8);
            cp16(base + TILE_B + so, B + (size_t)(block_n + r) * K + k0 + c * 8);
        }
    };

    load_stage(0, 0);
    CP_COMMIT();

    for (int i = 0; i < nK; i++) {
        CP_WAIT(0);
        __syncthreads();

        if (i + 1 < nK) load_stage(i + 1, (i + 1) & 1);
        CP_COMMIT();

        const uint32_t tA = stg(i & 1);
        const uint32_t tB = tA + TILE_B;

#pragma unroll
        for (int ks = 0; ks < 2; ks++) {
            const uint32_t kb = ks * 32;
            uint32_t af[2][4];
#pragma unroll
            for (int mt = 0; mt < 2; mt++)
                ldsm4(af[mt][0], af[mt][1], af[mt][2], af[mt][3], tA + a_off[mt] + kb);
#pragma unroll
            for (int nt2 = 0; nt2 < 4; nt2++) {
                uint32_t bf[2][2];
                ldsm4(bf[0][0], bf[0][1], bf[1][0], bf[1][1], tB + b_off[nt2] + kb);
#pragma unroll
                for (int h = 0; h < 2; h++) {
                    const int nt = 2 * nt2 + h;
#pragma unroll
                    for (int mt = 0; mt < 2; mt++)
                        mma_f16(acc[mt][nt], af[mt], bf[h]);
                }
            }
        }
    }

    // ---------------- epilogue: bias + PReLU ------------------------------
#pragma unroll
    for (int mt = 0; mt < 2; mt++) {
        const int r0 = block_m + warp_m + mt * 16 + gid;
#pragma unroll
        for (int nt = 0; nt < 8; nt++) {
            const int n = block_n + warp_n + nt * 8 + tg * 2;
            const float b0 = __ldg(&bias[n]),  b1 = __ldg(&bias[n + 1]);
            const float p0 = __ldg(&alpha[n]), p1 = __ldg(&alpha[n + 1]);
#pragma unroll
            for (int half = 0; half < 2; half++) {
                const int r = r0 + half * 8;
                float v0 = acc[mt][nt][half * 2 + 0] + b0;
                float v1 = acc[mt][nt][half * 2 + 1] + b1;
                v0 = v0 >= 0.f ? v0 : p0 * v0;
                v1 = v1 >= 0.f ? v1 : p1 * v1;
                if (OUT_HALF) {
                    __half2 hh;
                    hh.x = __float2half_rn(v0);
                    hh.y = __float2half_rn(v1);
                    *reinterpret_cast<__half2*>(&outH[(size_t)r * N + n]) = hh;
                } else {
                    float2 o; o.x = v0; o.y = v1;
                    *reinterpret_cast<float2*>(&outF[(size_t)r * N + n]) = o;
                }
            }
        }
    }
}

// ------------------------------ launch -------------------------------------
extern "C" void kernel_launch(void* const* d_in, const int* in_sizes, int n_in,
                              void* d_out, int out_size) {
    const float* x       = (const float*)d_in[0];
    const float* weights = (const float*)d_in[1];
    const float* W0 = (const float*)d_in[2];
    const float* b0 = (const float*)d_in[3];
    const float* a0 = (const float*)d_in[4];
    const float* W1 = (const float*)d_in[5];
    const float* b1 = (const float*)d_in[6];
    const float* a1 = (const float*)d_in[7];
    const float* W2 = (const float*)d_in[8];
    const float* b2 = (const float*)d_in[9];
    const float* a2 = (const float*)d_in[10];
    float* out = (float*)d_out;

    auto sym = [](const void* s) {
        void* p = nullptr;
        cudaGetSymbolAddress(&p, (const void*)s);
        return p;
    };
    __half* xh   = (__half*)sym(g_xh);
    __half* act0 = (__half*)sym(g_a0);
    __half* wt0  = (__half*)sym(g_wt0);
    __half* wt1  = (__half*)sym(g_wt1);
    __half* wt2  = (__half*)sym(g_wt2);
    float* bm0 = (float*)sym(g_bm0);
    float* bm1 = (float*)sym(g_bm1);
    float* bm2 = (float*)sym(g_bm2);

    cudaFuncSetAttribute(gemm_hmma<1>, cudaFuncAttributeMaxDynamicSharedMemorySize, SMEM_DYN);
    cudaFuncSetAttribute(gemm_hmma<0>, cudaFuncAttributeMaxDynamicSharedMemorySize, SMEM_DYN);

    // side stream + events, created once (deterministic work per call)
    static cudaStream_t s1 = nullptr;
    static cudaEvent_t evFork = nullptr, evCast = nullptr, evM1 = nullptr, evM2 = nullptr;
    if (s1 == nullptr) {
        cudaStreamCreateWithFlags(&s1, cudaStreamNonBlocking);
        cudaEventCreateWithFlags(&evFork, cudaEventDisableTiming);
        cudaEventCreateWithFlags(&evCast, cudaEventDisableTiming);
        cudaEventCreateWithFlags(&evM1, cudaEventDisableTiming);
        cudaEventCreateWithFlags(&evM2, cudaEventDisableTiming);
    }

    // fork side stream off the main stream's current front
    cudaEventRecord(evFork, 0);
    cudaStreamWaitEvent(s1, evFork, 0);

    // side stream: cast (only needs x) runs concurrent with merge0 on main;
    // then merges for layers 1, 2 overlap gemm0/gemm1.
    cast_x<<<(8192 * 512 / 4 + 255) / 256, 256, 0, s1>>>(
        (const float4*)x, (__half2*)xh, 8192 * 512 / 4);
    cudaEventRecord(evCast, s1);
    merge_w<<<dim3(1024 / 32, 1024 / 32), 256, 0, s1>>>(weights, W1, b1, wt1, bm1, 1024, 1024);
    cudaEventRecord(evM1, s1);
    merge_w<<<dim3(1024 / 32, 512 / 32), 256, 0, s1>>>(weights, W2, b2, wt2, bm2, 1024, 512);
    cudaEventRecord(evM2, s1);

    // main stream: merge0 concurrent with cast
    merge_w<<<dim3(512 / 32, 1024 / 32), 256>>>(weights, W0, b0, wt0, bm0, 512, 1024);

    // layer 0 (needs merge0 + cast)
    cudaStreamWaitEvent(0, evCast, 0);
    gemm_hmma<1><<<dim3(1024 / 128, M_ROWS / 128), 256, SMEM_DYN>>>(
        xh, wt0, bm0, a0, nullptr, act0, M_ROWS, 1024, 512);

    // layer 1 (needs merge1)
    cudaStreamWaitEvent(0, evM1, 0);
    gemm_hmma<1><<<dim3(1024 / 128, M_ROWS / 128), 256, SMEM_DYN>>>(
        act0, wt1, bm1, a1, nullptr, xh, M_ROWS, 1024, 1024);

    // layer 2 (needs merge2) -> fp32 out; joins side stream back into main
    cudaStreamWaitEvent(0, evM2, 0);
    gemm_hmma<0><<<dim3(512 / 128, M_ROWS / 128), 256, SMEM_DYN>>>(
        xh, wt2, bm2, a2, out, nullptr, M_ROWS, 512, 1024);
}